// round 1
// baseline (speedup 1.0000x reference)
#include <cuda_runtime.h>
#include <cuda_bf16.h>
#include <math.h>

// Problem constants
#define B_ 4
#define N_ 256
#define D_ 512
#define H_ 8
#define HD_ 64
#define KSP_ 25

// ---------------- scratch arena (no allocations allowed) ----------------
// offsets in floats
#define OFF_QKV   0u                                   // 4*256*1536 = 1572864
#define OFF_S     1572864u                             // 4*8*256*256 = 2097152
#define OFF_ATT   3670016u                             // 524288
#define OFF_A0    4194304u                             // 524288
#define OFF_A1    4718592u                             // 262144
#define OFF_A2    4980736u                             // 131072
#define OFF_CUR1  5111808u                             // 262144
#define OFF_CUR2  5373952u                             // 131072
#define OFF_P1    5505024u                             // 262144
#define OFF_P2    5767168u                             // 524288
#define OFF_CAT   6291456u                             // 1572864
#define OFF_HIER  7864320u                             // 524288
#define OFF_HI    8388608u                             // 524288
#define OFF_HJ    8912896u                             // 524288
#define OFF_ESC   9437184u                             // 262144
#define SCRATCH_TOTAL 9699328u

__device__ float g_scratch[SCRATCH_TOTAL];

// ---------------- generic tiled fp32 GEMM: C = act(A[M,K] @ W[K,N] + bias) ---
// BM=BN=64, BK=16, 256 threads, 4x4 per thread. M,N % 64 == 0, K % 16 == 0.
template<int ACT>
__global__ __launch_bounds__(256)
void gemm_bias(const float* __restrict__ A, const float* __restrict__ W,
               const float* __restrict__ bias, float* __restrict__ C,
               int M, int N, int K)
{
    __shared__ float As[16][64];
    __shared__ float Ws[16][64];
    const int tid = threadIdx.x;
    const int tx = tid & 15, ty = tid >> 4;
    const int row0 = blockIdx.y * 64, col0 = blockIdx.x * 64;

    const int arow = tid >> 2;           // 0..63
    const int ak   = (tid & 3) * 4;      // 0,4,8,12
    const int wk   = tid >> 4;           // 0..15
    const int wcol = (tid & 15) * 4;     // 0..60

    float acc[4][4] = {};

    for (int k0 = 0; k0 < K; k0 += 16) {
        float4 av = *(const float4*)&A[(size_t)(row0 + arow) * K + k0 + ak];
        As[ak + 0][arow] = av.x;
        As[ak + 1][arow] = av.y;
        As[ak + 2][arow] = av.z;
        As[ak + 3][arow] = av.w;
        *(float4*)&Ws[wk][wcol] = *(const float4*)&W[(size_t)(k0 + wk) * N + col0 + wcol];
        __syncthreads();
        #pragma unroll
        for (int k = 0; k < 16; k++) {
            float4 a4 = *(float4*)&As[k][ty * 4];
            float4 b4 = *(float4*)&Ws[k][tx * 4];
            const float a[4] = {a4.x, a4.y, a4.z, a4.w};
            const float b[4] = {b4.x, b4.y, b4.z, b4.w};
            #pragma unroll
            for (int i = 0; i < 4; i++)
                #pragma unroll
                for (int j = 0; j < 4; j++)
                    acc[i][j] += a[i] * b[j];
        }
        __syncthreads();
    }

    #pragma unroll
    for (int i = 0; i < 4; i++) {
        const int r = row0 + ty * 4 + i;
        float4 o;
        float* po = (float*)&o;
        #pragma unroll
        for (int j = 0; j < 4; j++) {
            float v = acc[i][j];
            if (bias) v += bias[col0 + tx * 4 + j];
            if (ACT == 1) v = fmaxf(v, 0.f);
            po[j] = v;
        }
        *(float4*)&C[(size_t)r * N + col0 + tx * 4] = o;
    }
}

// ---------------- attention: S[b,h,i,j] = 0.125 * q_i . k_j ------------------
// qkv layout: [B, n, 1536] with q at col h*64, k at 512+h*64, v at 1024+h*64
__global__ __launch_bounds__(256)
void attn_scores(const float* __restrict__ qkv, float* __restrict__ S, int n)
{
    const int bh = blockIdx.z;
    const int b = bh >> 3, h = bh & 7;
    const int i0 = blockIdx.y * 32, j0 = blockIdx.x * 32;
    __shared__ float Qs[32][65];
    __shared__ float Ks[32][65];
    const int tid = threadIdx.x;

    const float* qbase = qkv + (size_t)b * n * 1536 + h * 64;
    const float* kbase = qbase + 512;
    #pragma unroll
    for (int t = 0; t < 2; t++) {
        int fi = tid + t * 256;          // 0..511
        int r = fi >> 4;                 // row
        int c = (fi & 15) * 4;           // col
        float4 qv = *(const float4*)&qbase[(size_t)(i0 + r) * 1536 + c];
        Qs[r][c] = qv.x; Qs[r][c + 1] = qv.y; Qs[r][c + 2] = qv.z; Qs[r][c + 3] = qv.w;
        float4 kv = *(const float4*)&kbase[(size_t)(j0 + r) * 1536 + c];
        Ks[r][c] = kv.x; Ks[r][c + 1] = kv.y; Ks[r][c + 2] = kv.z; Ks[r][c + 3] = kv.w;
    }
    __syncthreads();

    const int tx = tid & 15, ty = tid >> 4;
    float acc[2][2] = {};
    #pragma unroll
    for (int k = 0; k < 64; k++) {
        float a0 = Qs[ty * 2][k], a1 = Qs[ty * 2 + 1][k];
        float b0 = Ks[tx * 2][k], b1 = Ks[tx * 2 + 1][k];
        acc[0][0] += a0 * b0; acc[0][1] += a0 * b1;
        acc[1][0] += a1 * b0; acc[1][1] += a1 * b1;
    }
    float* out = S + (size_t)bh * n * n;
    #pragma unroll
    for (int i = 0; i < 2; i++)
        #pragma unroll
        for (int j = 0; j < 2; j++)
            out[(size_t)(i0 + ty * 2 + i) * n + j0 + tx * 2 + j] = acc[i][j] * 0.125f;
}

// ---------------- softmax over rows of length n = RPT*32 --------------------
template<int RPT>
__global__ __launch_bounds__(256)
void softmax_rows(float* __restrict__ S, int rows)
{
    const int warp = (blockIdx.x * 256 + threadIdx.x) >> 5;
    const int lane = threadIdx.x & 31;
    if (warp >= rows) return;
    float* row = S + (size_t)warp * (RPT * 32);
    float v[RPT];
    float mx = -1e30f;
    #pragma unroll
    for (int t = 0; t < RPT; t++) { v[t] = row[lane + 32 * t]; mx = fmaxf(mx, v[t]); }
    #pragma unroll
    for (int o = 16; o; o >>= 1) mx = fmaxf(mx, __shfl_xor_sync(0xffffffffu, mx, o));
    float s = 0.f;
    #pragma unroll
    for (int t = 0; t < RPT; t++) { v[t] = expf(v[t] - mx); s += v[t]; }
    #pragma unroll
    for (int o = 16; o; o >>= 1) s += __shfl_xor_sync(0xffffffffu, s, o);
    const float inv = 1.f / s;
    #pragma unroll
    for (int t = 0; t < RPT; t++) row[lane + 32 * t] = v[t] * inv;
}

// ---------------- O[b,i,h,:] = P[b,h,i,:] @ V[b,h,:,:] ----------------------
__global__ __launch_bounds__(256)
void attn_pv(const float* __restrict__ S, const float* __restrict__ qkv,
             float* __restrict__ att, int n)
{
    const int bh = blockIdx.y;
    const int b = bh >> 3, h = bh & 7;
    const int i0 = blockIdx.x * 32;
    __shared__ float Ps[32][33];
    __shared__ float Vs[32][68];
    const int tid = threadIdx.x;
    const int tx = tid & 15, ty = tid >> 4;

    const float* P = S + (size_t)bh * n * n;
    const float* vbase = qkv + (size_t)b * n * 1536 + 1024 + h * 64;

    float acc[2][4] = {};
    for (int k0 = 0; k0 < n; k0 += 32) {
        {
            int r = tid >> 3, c = (tid & 7) * 4;
            float4 pv = *(const float4*)&P[(size_t)(i0 + r) * n + k0 + c];
            Ps[r][c] = pv.x; Ps[r][c + 1] = pv.y; Ps[r][c + 2] = pv.z; Ps[r][c + 3] = pv.w;
        }
        #pragma unroll
        for (int t = 0; t < 2; t++) {
            int fi = tid + t * 256;       // 0..511
            int r = fi >> 4, c = (fi & 15) * 4;
            *(float4*)&Vs[r][c] = *(const float4*)&vbase[(size_t)(k0 + r) * 1536 + c];
        }
        __syncthreads();
        #pragma unroll
        for (int k = 0; k < 32; k++) {
            float a0 = Ps[ty * 2][k], a1 = Ps[ty * 2 + 1][k];
            float4 b4 = *(float4*)&Vs[k][tx * 4];
            acc[0][0] += a0 * b4.x; acc[0][1] += a0 * b4.y;
            acc[0][2] += a0 * b4.z; acc[0][3] += a0 * b4.w;
            acc[1][0] += a1 * b4.x; acc[1][1] += a1 * b4.y;
            acc[1][2] += a1 * b4.z; acc[1][3] += a1 * b4.w;
        }
        __syncthreads();
    }
    #pragma unroll
    for (int i = 0; i < 2; i++) {
        float4 o = make_float4(acc[i][0], acc[i][1], acc[i][2], acc[i][3]);
        *(float4*)&att[(size_t)(b * n + i0 + ty * 2 + i) * 512 + h * 64 + tx * 4] = o;
    }
}

// ---------------- pairwise pooling mean -------------------------------------
__global__ void pair_mean(const float* __restrict__ p, float* __restrict__ out, int total)
{
    int i = blockIdx.x * blockDim.x + threadIdx.x;
    if (i >= total) return;
    int d = i & 511;
    int row = i >> 9;
    out[i] = 0.5f * (p[((size_t)(2 * row)) * 512 + d] + p[((size_t)(2 * row + 1)) * 512 + d]);
}

// ---------------- upsample + concat -----------------------------------------
__global__ void concat_up(const float* __restrict__ a0, const float* __restrict__ a1,
                          const float* __restrict__ a2, float* __restrict__ cat)
{
    int i = blockIdx.x * blockDim.x + threadIdx.x;
    if (i >= B_ * N_ * 1536) return;
    int c = i % 1536;
    int row = i / 1536;
    int b = row >> 8, node = row & 255;
    float v;
    if (c < 512)       v = a0[(size_t)row * 512 + c];
    else if (c < 1024) v = a1[(size_t)(b * 128 + (node >> 1)) * 512 + (c - 512)];
    else               v = a2[(size_t)(b * 64 + (node >> 2)) * 512 + (c - 1024)];
    cat[i] = v;
}

// ---------------- LayerNorm over rows of 512 (input already relu'd) ---------
__global__ __launch_bounds__(256)
void ln_rows(const float* __restrict__ Hp, const float* __restrict__ g,
             const float* __restrict__ bb, float* __restrict__ out, int rows)
{
    const int warp = (blockIdx.x * 256 + threadIdx.x) >> 5;
    const int lane = threadIdx.x & 31;
    if (warp >= rows) return;
    const float* row = Hp + (size_t)warp * 512;
    float v[16];
    float s = 0.f;
    #pragma unroll
    for (int t = 0; t < 16; t++) { v[t] = row[lane + 32 * t]; s += v[t]; }
    #pragma unroll
    for (int o = 16; o; o >>= 1) s += __shfl_xor_sync(0xffffffffu, s, o);
    const float mean = s * (1.f / 512.f);
    float var = 0.f;
    #pragma unroll
    for (int t = 0; t < 16; t++) { float d = v[t] - mean; var += d * d; }
    #pragma unroll
    for (int o = 16; o; o >>= 1) var += __shfl_xor_sync(0xffffffffu, var, o);
    var *= (1.f / 512.f);
    const float inv = rsqrtf(var + 1e-5f);
    float* o_ = out + (size_t)warp * 512;
    #pragma unroll
    for (int t = 0; t < 16; t++) {
        int c = lane + 32 * t;
        o_[c] = (v[t] - mean) * inv * g[c] + bb[c];
    }
}

// ---------------- edge scores: sigmoid(relu(hi_i + hj_j) . We2 + be2) -------
// block handles (b, 8 rows i); warp w handles j in [w*32, w*32+32)
__global__ __launch_bounds__(256)
void edge_scores(const float* __restrict__ hi, const float* __restrict__ hj,
                 const float* __restrict__ We2, const float* __restrict__ be2,
                 float* __restrict__ esc)
{
    __shared__ float his[8][512];
    __shared__ float w2s[512];
    const int blk = blockIdx.x;
    const int b = blk >> 5;
    const int i0 = (blk & 31) * 8;
    const int tid = threadIdx.x;
    #pragma unroll
    for (int q = 0; q < 4; q++) {
        int fi = tid + 256 * q;            // float4 index 0..1023
        int r = fi >> 7;
        int c = (fi & 127) * 4;
        *(float4*)&his[r][c] = *(const float4*)&hi[(size_t)(b * 256 + i0 + r) * 512 + c];
    }
    w2s[tid] = We2[tid];
    w2s[tid + 256] = We2[tid + 256];
    __syncthreads();

    const int w = tid >> 5, lane = tid & 31;
    const float be2v = be2[0];
    const float* hjb = hj + (size_t)b * 256 * 512;
    for (int jj = 0; jj < 32; jj++) {
        const int j = w * 32 + jj;
        const float* hjr = hjb + (size_t)j * 512;
        float acc[8] = {};
        #pragma unroll 4
        for (int q = 0; q < 16; q++) {
            int d = lane + 32 * q;
            float hv = hjr[d];
            float w2 = w2s[d];
            #pragma unroll
            for (int i = 0; i < 8; i++)
                acc[i] += fmaxf(his[i][d] + hv, 0.f) * w2;
        }
        #pragma unroll
        for (int i = 0; i < 8; i++) {
            float a = acc[i];
            #pragma unroll
            for (int o = 16; o; o >>= 1) a += __shfl_xor_sync(0xffffffffu, a, o);
            acc[i] = a;
        }
        if (lane == 0) {
            #pragma unroll
            for (int i = 0; i < 8; i++) {
                int ii = i0 + i;
                float s = (j == ii) ? 0.f : 1.f / (1.f + expf(-(acc[i] + be2v)));
                esc[((size_t)(b * 256 + ii)) * 256 + j] = s;
            }
        }
    }
}

// ---------------- top-25 per row (warp per row), jax tie-break --------------
__global__ __launch_bounds__(256)
void topk_rows(const float* __restrict__ scores, float* __restrict__ adj)
{
    const int warp = (blockIdx.x * 256 + threadIdx.x) >> 5;
    const int lane = threadIdx.x & 31;
    if (warp >= B_ * N_) return;
    const float* row = scores + (size_t)warp * N_;
    float v[8];
    #pragma unroll
    for (int t = 0; t < 8; t++) v[t] = row[lane + 32 * t];
    float* arow = adj + (size_t)warp * N_;
    for (int k = 0; k < KSP_; k++) {
        float bv = -1e30f; int bi = 0x7fffffff;
        #pragma unroll
        for (int t = 0; t < 8; t++) {
            int idx = lane + 32 * t;
            if (v[t] > bv) { bv = v[t]; bi = idx; }
        }
        #pragma unroll
        for (int o = 16; o; o >>= 1) {
            float ov = __shfl_xor_sync(0xffffffffu, bv, o);
            int   oi = __shfl_xor_sync(0xffffffffu, bi, o);
            if (ov > bv || (ov == bv && oi < bi)) { bv = ov; bi = oi; }
        }
        if (lane == (bi & 31)) v[bi >> 5] = -1e30f;
        if (lane == 0) arow[bi] = 1.0f;
    }
}

// ---------------- zero fill -------------------------------------------------
__global__ void zero_fill(float* __restrict__ p, int n)
{
    int i = blockIdx.x * blockDim.x + threadIdx.x;
    if (i < n) p[i] = 0.f;
}

// ---------------- host orchestration ----------------------------------------
static void run_mha(const float* cur, const float* Wqkv, const float* bqkv,
                    const float* Wo, const float* bo, float* out,
                    float* qkv, float* S, float* att, int n)
{
    const int M = B_ * n;
    gemm_bias<0><<<dim3(1536 / 64, M / 64), 256>>>(cur, Wqkv, bqkv, qkv, M, 1536, 512);
    attn_scores<<<dim3(n / 32, n / 32, B_ * H_), 256>>>(qkv, S, n);
    const int rows = B_ * H_ * n;
    if (n == 256)      softmax_rows<8><<<rows / 8, 256>>>(S, rows);
    else if (n == 128) softmax_rows<4><<<rows / 8, 256>>>(S, rows);
    else               softmax_rows<2><<<rows / 8, 256>>>(S, rows);
    attn_pv<<<dim3(n / 32, B_ * H_), 256>>>(S, qkv, att, n);
    gemm_bias<0><<<dim3(512 / 64, M / 64), 256>>>(att, Wo, bo, out, M, 512, 512);
}

extern "C" void kernel_launch(void* const* d_in, const int* in_sizes, int n_in,
                              void* d_out, int out_size)
{
    const float* x      = (const float*)d_in[0];
    // d_in[1] = adjacency (unused by reference)
    const float* Wqkv   = (const float*)d_in[2];
    const float* bqkv   = (const float*)d_in[3];
    const float* Wo     = (const float*)d_in[4];
    const float* bo     = (const float*)d_in[5];
    const float* Wp1    = (const float*)d_in[6];
    const float* bp1    = (const float*)d_in[7];
    const float* Wp2    = (const float*)d_in[8];
    const float* bp2    = (const float*)d_in[9];
    const float* Wfuse  = (const float*)d_in[10];
    const float* bfuse  = (const float*)d_in[11];
    const float* ln_g   = (const float*)d_in[12];
    const float* ln_b   = (const float*)d_in[13];
    const float* We1    = (const float*)d_in[14];
    const float* be1    = (const float*)d_in[15];
    const float* We2    = (const float*)d_in[16];
    const float* be2    = (const float*)d_in[17];
    const float* Ws_qkv = (const float*)d_in[18];
    const float* bs_qkv = (const float*)d_in[19];
    const float* Ws_o   = (const float*)d_in[20];
    const float* bs_o   = (const float*)d_in[21];
    float* out = (float*)d_out;

    float* sc = nullptr;
    cudaGetSymbolAddress((void**)&sc, g_scratch);
    float* qkv  = sc + OFF_QKV;
    float* S    = sc + OFF_S;
    float* att  = sc + OFF_ATT;
    float* a0   = sc + OFF_A0;
    float* a1   = sc + OFF_A1;
    float* a2   = sc + OFF_A2;
    float* cur1 = sc + OFF_CUR1;
    float* cur2 = sc + OFF_CUR2;
    float* p1   = sc + OFF_P1;
    float* p2   = sc + OFF_P2;
    float* cat  = sc + OFF_CAT;
    float* hier = sc + OFF_HIER;
    float* hi   = sc + OFF_HI;
    float* hj   = sc + OFF_HJ;
    float* esc  = sc + OFF_ESC;

    // ---- hierarchy ----
    const int ns[3] = {256, 128, 64};
    float* aouts[3] = {a0, a1, a2};
    float* curbuf[2] = {cur1, cur2};
    const float* cur = x;
    for (int l = 0; l < 3; l++) {
        const int n = ns[l];
        const int M = B_ * n;
        run_mha(cur, Wqkv + (size_t)l * 512 * 1536, bqkv + l * 1536,
                Wo + (size_t)l * 512 * 512, bo + l * 512, aouts[l], qkv, S, att, n);
        if (l < 2) {
            gemm_bias<1><<<dim3(256 / 64, M / 64), 256>>>(
                aouts[l], Wp1 + (size_t)l * 512 * 256, bp1 + l * 256, p1, M, 256, 512);
            gemm_bias<0><<<dim3(512 / 64, M / 64), 256>>>(
                p1, Wp2 + (size_t)l * 256 * 512, bp2 + l * 512, p2, M, 512, 256);
            const int total = (M / 2) * 512;
            pair_mean<<<(total + 255) / 256, 256>>>(p2, curbuf[l], total);
            cur = curbuf[l];
        }
    }

    // ---- fuse + LN ----
    concat_up<<<(B_ * N_ * 1536) / 256, 256>>>(a0, a1, a2, cat);
    gemm_bias<1><<<dim3(512 / 64, 1024 / 64), 256>>>(cat, Wfuse, bfuse, p2, 1024, 512, 1536);
    ln_rows<<<1024 / 8, 256>>>(p2, ln_g, ln_b, hier, 1024);

    // ---- edge scoring + top-k ----
    gemm_bias<0><<<dim3(512 / 64, 1024 / 64), 256>>>(hier, We1, nullptr, hi, 1024, 512, 512);
    gemm_bias<0><<<dim3(512 / 64, 1024 / 64), 256>>>(hier, We1 + 512 * 512, be1, hj, 1024, 512, 512);
    edge_scores<<<B_ * (N_ / 8), 256>>>(hi, hj, We2, be2, esc);
    float* adj_out = out + (size_t)B_ * N_ * D_;      // after attended
    zero_fill<<<(B_ * N_ * N_ + 255) / 256, 256>>>(adj_out, B_ * N_ * N_);
    topk_rows<<<(B_ * N_) / 8, 256>>>(esc, adj_out);

    // ---- final sparse-path MHA -> attended (first output region) ----
    run_mha(hier, Ws_qkv, bs_qkv, Ws_o, bs_o, out, qkv, S, att, 256);
}